// round 4
// baseline (speedup 1.0000x reference)
#include <cuda_runtime.h>
#include <cuda_bf16.h>

// TopKPool fully fused single kernel with software last-block-per-row barrier:
//   512 blocks stream embeddings for masked linear scores (6.05 TB/s path from R2/R3).
//   The last-arriving block per batch row runs the tail (top-k + indicators + pooling)
//   overlapped with other rows' streaming — no second kernel launch, no serialized tail.
// Output layout: [pooled (B*D) | attn_weights (B*K)], fp32.

#define NEG_INF (-1e30f)
#define SENTINEL (-2e30f)

constexpr int Bv = 128;
constexpr int Kv = 512;
constexpr int Dv = 768;
constexpr int D4 = Dv / 4;           // 192 float4 per row
constexpr int MAX_TOPK = 64;

constexpr int SPLIT = 4;             // K-segments per batch row
constexpr int KSEG  = Kv / SPLIT;    // 128 rows per block
constexpr int T1    = 256;           // 8 warps

__device__ float g_scores[Bv * Kv];  // 256 KB scratch (static device global)
__device__ int   g_count[Bv];        // zero-init; self-resetting per launch

__global__ __launch_bounds__(T1)
void topkpool_fused(const float* __restrict__ emb,
                    const int*   __restrict__ mask,
                    const float* __restrict__ w,
                    const float* __restrict__ bias,
                    const int*   __restrict__ topk,
                    float*       __restrict__ out)
{
    __shared__ __align__(16) float s_w[Dv];
    __shared__ int s_top[MAX_TOPK];
    __shared__ int s_last;

    const int tid  = threadIdx.x;
    const int lane = tid & 31;
    const int wid  = tid >> 5;

    for (int i = tid; i < Dv; i += T1) s_w[i] = w[i];
    __syncthreads();

    const int b   = blockIdx.x / SPLIT;
    const int seg = blockIdx.x % SPLIT;
    const int k0  = seg * KSEG;

    const float bval = bias[0];
    const float* eb  = emb + (size_t)b * Kv * Dv;
    const float4* wv = (const float4*)s_w;

    float* out_pool = out;                      // (B, D)
    float* out_attn = out + (size_t)Bv * Dv;    // (B, K)

    // ---- phase 1: scoring (8 warps x 8 iters x 2 rows = 128 rows) ----
    for (int kk = wid; kk < KSEG / 2; kk += 8) {
        const int ka = k0 + kk;
        const int kb = k0 + kk + KSEG / 2;
        const float4* ra = (const float4*)(eb + (size_t)ka * Dv);
        const float4* rb = (const float4*)(eb + (size_t)kb * Dv);

        float acc_a = 0.f, acc_b = 0.f;
        #pragma unroll
        for (int j = 0; j < 6; j++) {
            float4 ea  = __ldcs(&ra[j * 32 + lane]);
            float4 eb4 = __ldcs(&rb[j * 32 + lane]);
            float4 ww  = wv[j * 32 + lane];
            acc_a += ea.x * ww.x + ea.y * ww.y + ea.z * ww.z + ea.w * ww.w;
            acc_b += eb4.x* ww.x + eb4.y* ww.y + eb4.z* ww.z + eb4.w* ww.w;
        }
        #pragma unroll
        for (int off = 16; off; off >>= 1) {
            acc_a += __shfl_xor_sync(0xFFFFFFFFu, acc_a, off);
            acc_b += __shfl_xor_sync(0xFFFFFFFFu, acc_b, off);
        }
        if (lane == 0) {
            float sa = acc_a + bval;
            float sb = acc_b + bval;
            if (mask[(size_t)b * Kv + ka] == 0) sa = NEG_INF;
            if (mask[(size_t)b * Kv + kb] == 0) sb = NEG_INF;
            g_scores[(size_t)b * Kv + ka] = sa;
            g_scores[(size_t)b * Kv + kb] = sb;
        }
    }

    // zero this block's chunk of the attn row (d_out is poisoned)
    for (int i = tid; i < KSEG; i += T1)
        out_attn[(size_t)b * Kv + k0 + i] = 0.f;

    // ---- software barrier: last block per row takes the tail ----
    __threadfence();
    __syncthreads();
    if (tid == 0) {
        int old = atomicAdd(&g_count[b], 1);
        s_last = (old == SPLIT - 1);
        if (s_last) g_count[b] = 0;             // reset for next graph replay
    }
    __syncthreads();
    if (!s_last) return;

    // ---- tail: top-k (warp 0, register-resident, no block barriers) ----
    int ksel = topk[0];
    if (ksel > Kv) ksel = Kv;
    if (ksel < 1)  ksel = 1;
    if (ksel > MAX_TOPK) ksel = MAX_TOPK;

    if (wid == 0) {
        float v[16];
        const float* sc = g_scores + (size_t)b * Kv;
        #pragma unroll
        for (int j = 0; j < 16; j++) v[j] = __ldcg(&sc[lane + 32 * j]);

        for (int m = 0; m < ksel; m++) {
            float bv = v[0]; int bj = 0;
            #pragma unroll
            for (int j = 1; j < 16; j++)
                if (v[j] > bv) { bv = v[j]; bj = j; }   // ties: lowest j
            int bidx = lane + 32 * bj;
            #pragma unroll
            for (int off = 16; off; off >>= 1) {
                float v2 = __shfl_xor_sync(0xFFFFFFFFu, bv, off);
                int   i2 = __shfl_xor_sync(0xFFFFFFFFu, bidx, off);
                if (v2 > bv || (v2 == bv && i2 < bidx)) { bv = v2; bidx = i2; }
            }
            if (lane == (bidx & 31)) v[bidx >> 5] = SENTINEL;
            if (lane == 0) s_top[m] = bidx;
        }
    }
    __syncthreads();

    const float inv = 1.f / (float)ksel;
    if (tid < ksel)
        out_attn[(size_t)b * Kv + s_top[tid]] = inv;

    // ---- pooling: 192 threads, one float4 column each ----
    if (tid < D4) {
        const float4* ebv = (const float4*)eb;
        float4 sum = make_float4(0.f, 0.f, 0.f, 0.f);
        if (ksel == 8) {
            int t[8];
            #pragma unroll
            for (int m = 0; m < 8; m++) t[m] = s_top[m];
            #pragma unroll
            for (int m = 0; m < 8; m++) {
                float4 e = __ldg(&ebv[(size_t)t[m] * D4 + tid]);
                sum.x += e.x; sum.y += e.y; sum.z += e.z; sum.w += e.w;
            }
        } else {
            #pragma unroll 4
            for (int m = 0; m < ksel; m++) {
                float4 e = __ldg(&ebv[(size_t)s_top[m] * D4 + tid]);
                sum.x += e.x; sum.y += e.y; sum.z += e.z; sum.w += e.w;
            }
        }
        float4 r = make_float4(sum.x * inv, sum.y * inv, sum.z * inv, sum.w * inv);
        ((float4*)(out_pool + (size_t)b * Dv))[tid] = r;
    }
}

extern "C" void kernel_launch(void* const* d_in, const int* in_sizes, int n_in,
                              void* d_out, int out_size)
{
    const float* emb  = (const float*)d_in[0];
    const int*   mask = (const int*)  d_in[1];
    const float* w    = (const float*)d_in[2];
    const float* bias = (const float*)d_in[3];
    const int*   topk = (const int*)  d_in[4];
    float*       out  = (float*)d_out;
    (void)in_sizes; (void)n_in; (void)out_size;

    topkpool_fused<<<Bv * SPLIT, T1>>>(emb, mask, w, bias, topk, out);
}

// round 5
// speedup vs baseline: 1.0429x; 1.0429x over previous
#include <cuda_runtime.h>
#include <cuda_bf16.h>

// TopKPool, 2 kernels:
//   K1: masked linear scores, w held in registers (no LDS in inner loop),
//       per-segment top-ksel candidates computed in-block + attn-segment zeroing.
//   K2: merge 4*ksel candidates (one warp), indicator writes, float4 gather pooling.
// Output layout: [pooled (B*D) | attn_weights (B*K)], fp32.

#define NEG_INF  (-1e30f)
#define SENTINEL (-2e30f)

constexpr int Bv = 128;
constexpr int Kv = 512;
constexpr int Dv = 768;
constexpr int D4 = Dv / 4;           // 192 float4 per row
constexpr int MAX_TOPK = 64;

constexpr int SPLIT = 4;             // K-segments per batch row
constexpr int KSEG  = Kv / SPLIT;    // 128 rows per block
constexpr int T1    = 256;           // 8 warps
constexpr int T2    = 192;           // 6 warps (pooling width)

// candidate scratch: per (b, seg), up to MAX_TOPK (val, idx) pairs
__device__ float g_cval[Bv * SPLIT * MAX_TOPK];
__device__ int   g_cidx[Bv * SPLIT * MAX_TOPK];

__device__ __forceinline__ int clamp_ksel(int k) {
    if (k < 1) k = 1;
    if (k > MAX_TOPK) k = MAX_TOPK;
    return k;
}

// ---------------- K1: scoring + per-segment top-k ----------------
__global__ __launch_bounds__(T1)
void score_kernel(const float* __restrict__ emb,
                  const int*   __restrict__ mask,
                  const float* __restrict__ w,
                  const float* __restrict__ bias,
                  const int*   __restrict__ topk,
                  float*       __restrict__ out)
{
    __shared__ float s_sc[KSEG];

    const int tid  = threadIdx.x;
    const int lane = tid & 31;
    const int wid  = tid >> 5;

    const int b   = blockIdx.x / SPLIT;
    const int seg = blockIdx.x % SPLIT;
    const int k0  = seg * KSEG;

    // w in registers: 6 float4 per thread (lane-strided), loop-invariant
    const float4* wg = (const float4*)w;
    const float4 w0 = __ldg(&wg[  0 + lane]);
    const float4 w1 = __ldg(&wg[ 32 + lane]);
    const float4 w2 = __ldg(&wg[ 64 + lane]);
    const float4 w3 = __ldg(&wg[ 96 + lane]);
    const float4 w4 = __ldg(&wg[128 + lane]);
    const float4 w5 = __ldg(&wg[160 + lane]);

    const float  bval = __ldg(&bias[0]);
    const float* eb   = emb + (size_t)b * Kv * Dv;

    float* out_attn = out + (size_t)Bv * Dv;    // (B, K)

    // ---- scoring: 8 warps x 8 iters x 2 rows = 128 rows ----
    for (int kk = wid; kk < KSEG / 2; kk += 8) {
        const int ka = kk;
        const int kb = kk + KSEG / 2;
        const float4* ra = (const float4*)(eb + (size_t)(k0 + ka) * Dv);
        const float4* rb = (const float4*)(eb + (size_t)(k0 + kb) * Dv);

        float4 a0 = __ldcs(&ra[  0 + lane]);
        float4 a1 = __ldcs(&ra[ 32 + lane]);
        float4 a2 = __ldcs(&ra[ 64 + lane]);
        float4 a3 = __ldcs(&ra[ 96 + lane]);
        float4 a4 = __ldcs(&ra[128 + lane]);
        float4 a5 = __ldcs(&ra[160 + lane]);
        float4 b0 = __ldcs(&rb[  0 + lane]);
        float4 b1 = __ldcs(&rb[ 32 + lane]);
        float4 b2 = __ldcs(&rb[ 64 + lane]);
        float4 b3 = __ldcs(&rb[ 96 + lane]);
        float4 b4 = __ldcs(&rb[128 + lane]);
        float4 b5 = __ldcs(&rb[160 + lane]);

        float acc_a = a0.x*w0.x + a0.y*w0.y + a0.z*w0.z + a0.w*w0.w
                    + a1.x*w1.x + a1.y*w1.y + a1.z*w1.z + a1.w*w1.w
                    + a2.x*w2.x + a2.y*w2.y + a2.z*w2.z + a2.w*w2.w
                    + a3.x*w3.x + a3.y*w3.y + a3.z*w3.z + a3.w*w3.w
                    + a4.x*w4.x + a4.y*w4.y + a4.z*w4.z + a4.w*w4.w
                    + a5.x*w5.x + a5.y*w5.y + a5.z*w5.z + a5.w*w5.w;
        float acc_b = b0.x*w0.x + b0.y*w0.y + b0.z*w0.z + b0.w*w0.w
                    + b1.x*w1.x + b1.y*w1.y + b1.z*w1.z + b1.w*w1.w
                    + b2.x*w2.x + b2.y*w2.y + b2.z*w2.z + b2.w*w2.w
                    + b3.x*w3.x + b3.y*w3.y + b3.z*w3.z + b3.w*w3.w
                    + b4.x*w4.x + b4.y*w4.y + b4.z*w4.z + b4.w*w4.w
                    + b5.x*w5.x + b5.y*w5.y + b5.z*w5.z + b5.w*w5.w;

        #pragma unroll
        for (int off = 16; off; off >>= 1) {
            acc_a += __shfl_xor_sync(0xFFFFFFFFu, acc_a, off);
            acc_b += __shfl_xor_sync(0xFFFFFFFFu, acc_b, off);
        }
        if (lane == 0) {
            float sa = acc_a + bval;
            float sb = acc_b + bval;
            if (__ldg(&mask[(size_t)b * Kv + k0 + ka]) == 0) sa = NEG_INF;
            if (__ldg(&mask[(size_t)b * Kv + k0 + kb]) == 0) sb = NEG_INF;
            s_sc[ka] = sa;
            s_sc[kb] = sb;
        }
    }

    // zero this block's chunk of the attn row (d_out is poisoned)
    for (int i = tid; i < KSEG; i += T1)
        out_attn[(size_t)b * Kv + k0 + i] = 0.f;

    __syncthreads();

    // ---- per-segment top-ksel (warp 0, register tournament) ----
    if (wid == 0) {
        int ksel = clamp_ksel(__ldg(&topk[0]));

        float v[4];
        int   ix[4];
        #pragma unroll
        for (int j = 0; j < 4; j++) {
            v[j]  = s_sc[lane + 32 * j];
            ix[j] = k0 + lane + 32 * j;         // global k index
        }

        float* cv = g_cval + (size_t)(b * SPLIT + seg) * MAX_TOPK;
        int*   ci = g_cidx + (size_t)(b * SPLIT + seg) * MAX_TOPK;

        for (int m = 0; m < ksel; m++) {
            float bvv = v[0]; int bi = ix[0];
            #pragma unroll
            for (int j = 1; j < 4; j++)
                if (v[j] > bvv || (v[j] == bvv && ix[j] < bi)) { bvv = v[j]; bi = ix[j]; }
            #pragma unroll
            for (int off = 16; off; off >>= 1) {
                float v2 = __shfl_xor_sync(0xFFFFFFFFu, bvv, off);
                int   i2 = __shfl_xor_sync(0xFFFFFFFFu, bi, off);
                if (v2 > bvv || (v2 == bvv && i2 < bi)) { bvv = v2; bi = i2; }
            }
            #pragma unroll
            for (int j = 0; j < 4; j++)
                if (ix[j] == bi) v[j] = SENTINEL;
            if (lane == 0) { cv[m] = bvv; ci[m] = bi; }
        }
    }
}

// ---------------- K2: merge candidates + indicators + pooling ----------------
__global__ __launch_bounds__(T2)
void finish_kernel(const float* __restrict__ emb,
                   const int*   __restrict__ topk,
                   float*       __restrict__ out)
{
    __shared__ int s_top[MAX_TOPK];

    const int b    = blockIdx.x;
    const int tid  = threadIdx.x;
    const int lane = tid & 31;
    const int wid  = tid >> 5;

    int ksel = clamp_ksel(__ldg(&topk[0]));
    const int C = SPLIT * ksel;                 // <= 256 candidates

    if (wid == 0) {
        float v[8];
        int   ix[8];
        const float* cv = g_cval + (size_t)b * SPLIT * MAX_TOPK;
        const int*   ci = g_cidx + (size_t)b * SPLIT * MAX_TOPK;
        #pragma unroll
        for (int j = 0; j < 8; j++) {
            int n = lane + 32 * j;
            if (n < C) {
                int sg = n / ksel, m = n - sg * ksel;
                int a  = sg * MAX_TOPK + m;
                v[j]  = __ldcg(&cv[a]);
                ix[j] = __ldcg(&ci[a]);
            } else { v[j] = SENTINEL; ix[j] = 0x7FFFFFFF; }
        }

        for (int m = 0; m < ksel; m++) {
            float bvv = v[0]; int bi = ix[0];
            #pragma unroll
            for (int j = 1; j < 8; j++)
                if (v[j] > bvv || (v[j] == bvv && ix[j] < bi)) { bvv = v[j]; bi = ix[j]; }
            #pragma unroll
            for (int off = 16; off; off >>= 1) {
                float v2 = __shfl_xor_sync(0xFFFFFFFFu, bvv, off);
                int   i2 = __shfl_xor_sync(0xFFFFFFFFu, bi, off);
                if (v2 > bvv || (v2 == bvv && i2 < bi)) { bvv = v2; bi = i2; }
            }
            #pragma unroll
            for (int j = 0; j < 8; j++)
                if (ix[j] == bi) v[j] = SENTINEL;
            if (lane == 0) s_top[m] = bi;
        }
    }
    __syncthreads();

    float* out_pool = out;                      // (B, D)
    float* out_attn = out + (size_t)Bv * Dv;    // (B, K)

    const float inv = 1.f / (float)ksel;
    if (tid < ksel)
        out_attn[(size_t)b * Kv + s_top[tid]] = inv;   // row already zeroed by K1

    // pooling: 192 threads, one float4 column each
    const float4* ebv = (const float4*)(emb + (size_t)b * Kv * Dv);
    float4 sum = make_float4(0.f, 0.f, 0.f, 0.f);
    if (ksel == 8) {
        int t[8];
        #pragma unroll
        for (int m = 0; m < 8; m++) t[m] = s_top[m];
        #pragma unroll
        for (int m = 0; m < 8; m++) {
            float4 e = __ldg(&ebv[(size_t)t[m] * D4 + tid]);
            sum.x += e.x; sum.y += e.y; sum.z += e.z; sum.w += e.w;
        }
    } else {
        #pragma unroll 4
        for (int m = 0; m < ksel; m++) {
            float4 e = __ldg(&ebv[(size_t)s_top[m] * D4 + tid]);
            sum.x += e.x; sum.y += e.y; sum.z += e.z; sum.w += e.w;
        }
    }
    float4 r = make_float4(sum.x * inv, sum.y * inv, sum.z * inv, sum.w * inv);
    ((float4*)(out_pool + (size_t)b * Dv))[tid] = r;
}

extern "C" void kernel_launch(void* const* d_in, const int* in_sizes, int n_in,
                              void* d_out, int out_size)
{
    const float* emb  = (const float*)d_in[0];
    const int*   mask = (const int*)  d_in[1];
    const float* w    = (const float*)d_in[2];
    const float* bias = (const float*)d_in[3];
    const int*   topk = (const int*)  d_in[4];
    float*       out  = (float*)d_out;
    (void)in_sizes; (void)n_in; (void)out_size;

    score_kernel<<<Bv * SPLIT, T1>>>(emb, mask, w, bias, topk, out);
    finish_kernel<<<Bv, T2>>>(emb, topk, out);
}